// round 1
// baseline (speedup 1.0000x reference)
#include <cuda_runtime.h>

#define N_NODES 100000
#define N_EDGES 800000
#define DIM 128

// Scratch (allocation-free rule: __device__ globals)
__device__ float g_v[N_NODES * DIM];
__device__ float g_h[N_NODES * DIM];

// ---------------------------------------------------------------------------
// Typed GEMM: Y[n,:] = X[n,:] @ W[ntype[n]]   (W: [2,128,128] row-major)
// BM=64 rows/block, BN=128 (full width), BK=16. 256 threads, 4x8 per thread.
// ntype is sorted, so almost every block is single-type: run 1 pass with that
// weight. The (at most one) mixed block runs 2 passes and masks the writeout.
// ---------------------------------------------------------------------------
__global__ __launch_bounds__(256) void typed_gemm_kernel(
    const float* __restrict__ X, const float* __restrict__ W,
    const int* __restrict__ ntype, float* __restrict__ Y, int N)
{
    __shared__ float Xs[16][64];    // [kk][row]
    __shared__ float Ws[16][128];   // [kk][col]

    const int tx   = threadIdx.x;
    const int row0 = blockIdx.x * 64;
    const int cg   = tx & 15;   // col group: cols cg*8 .. cg*8+7
    const int rg   = tx >> 4;   // row group: rows rg*4 .. rg*4+3

    const int t0 = ntype[row0 < N ? row0 : N - 1];
    const int lastRow = (row0 + 63 < N) ? (row0 + 63) : (N - 1);
    const int t1 = ntype[lastRow];

    for (int t = t0; t <= t1; ++t) {
        const float* Wt = W + t * DIM * DIM;

        float acc[4][8];
        #pragma unroll
        for (int i = 0; i < 4; i++)
            #pragma unroll
            for (int j = 0; j < 8; j++) acc[i][j] = 0.f;

        for (int k0 = 0; k0 < DIM; k0 += 16) {
            // --- load X tile [64 rows x 16 k], store transposed Xs[kk][row]
            {
                const int r  = tx >> 2;         // 0..63
                const int kp = (tx & 3) * 4;    // 0,4,8,12
                const int grow = row0 + r;
                float4 xv = make_float4(0.f, 0.f, 0.f, 0.f);
                if (grow < N)
                    xv = *(const float4*)(X + (size_t)grow * DIM + k0 + kp);
                Xs[kp + 0][r] = xv.x;
                Xs[kp + 1][r] = xv.y;
                Xs[kp + 2][r] = xv.z;
                Xs[kp + 3][r] = xv.w;
            }
            // --- load W tile [16 x 128]: 512 float4 / 256 threads = 2 each
            {
                #pragma unroll
                for (int l = 0; l < 2; l++) {
                    const int f  = tx + l * 256;    // 0..511
                    const int kk = f >> 5;          // f / 32
                    const int c4 = f & 31;
                    float4 wv = *(const float4*)(Wt + (size_t)(k0 + kk) * DIM + c4 * 4);
                    *(float4*)(&Ws[kk][c4 * 4]) = wv;
                }
            }
            __syncthreads();

            #pragma unroll
            for (int kk = 0; kk < 16; kk++) {
                float a[4];
                #pragma unroll
                for (int i = 0; i < 4; i++) a[i] = Xs[kk][rg * 4 + i];
                const float4 b0 = *(const float4*)(&Ws[kk][cg * 8]);
                const float4 b1 = *(const float4*)(&Ws[kk][cg * 8 + 4]);
                const float b[8] = {b0.x, b0.y, b0.z, b0.w, b1.x, b1.y, b1.z, b1.w};
                #pragma unroll
                for (int i = 0; i < 4; i++)
                    #pragma unroll
                    for (int j = 0; j < 8; j++)
                        acc[i][j] = fmaf(a[i], b[j], acc[i][j]);
            }
            __syncthreads();
        }

        // --- writeout: only rows whose type matches this pass
        #pragma unroll
        for (int i = 0; i < 4; i++) {
            const int grow = row0 + rg * 4 + i;
            if (grow < N && ntype[grow] == t) {
                float4 o0 = make_float4(acc[i][0], acc[i][1], acc[i][2], acc[i][3]);
                float4 o1 = make_float4(acc[i][4], acc[i][5], acc[i][6], acc[i][7]);
                *(float4*)(Y + (size_t)grow * DIM + cg * 8)     = o0;
                *(float4*)(Y + (size_t)grow * DIM + cg * 8 + 4) = o1;
            }
        }
    }
}

// ---------------------------------------------------------------------------
// Edge scatter-sum: g_h[dst[e],:] += g_v[src[e],:]. One warp per edge.
// Each lane moves a float4 (32 lanes x 4 = 128 floats) with scalar atomics.
// ---------------------------------------------------------------------------
__global__ __launch_bounds__(256) void scatter_kernel(
    const int* __restrict__ src, const int* __restrict__ dst)
{
    const int w    = (int)((blockIdx.x * (unsigned)blockDim.x + threadIdx.x) >> 5);
    const int lane = threadIdx.x & 31;
    if (w >= N_EDGES) return;

    const int s = src[w];
    const int d = dst[w];

    const float4 x = ((const float4*)(g_v + (size_t)s * DIM))[lane];
    float* hd = g_h + (size_t)d * DIM + lane * 4;
    atomicAdd(hd + 0, x.x);
    atomicAdd(hd + 1, x.y);
    atomicAdd(hd + 2, x.z);
    atomicAdd(hd + 3, x.w);
}

// ---------------------------------------------------------------------------
__global__ __launch_bounds__(256) void zero_h_kernel()
{
    const int i = blockIdx.x * blockDim.x + threadIdx.x;
    const int total = N_NODES * DIM / 4;
    if (i < total)
        ((float4*)g_h)[i] = make_float4(0.f, 0.f, 0.f, 0.f);
}

// ---------------------------------------------------------------------------
extern "C" void kernel_launch(void* const* d_in, const int* in_sizes, int n_in,
                              void* d_out, int out_size)
{
    const float* x     = (const float*)d_in[0];
    const int*   ntype = (const int*)  d_in[1];
    const int*   src   = (const int*)  d_in[2];
    const int*   dst   = (const int*)  d_in[3];
    const float* W_v   = (const float*)d_in[4];
    const float* W_a   = (const float*)d_in[5];
    float*       out   = (float*)d_out;

    float *v_ptr, *h_ptr;
    cudaGetSymbolAddress((void**)&v_ptr, g_v);
    cudaGetSymbolAddress((void**)&h_ptr, g_h);

    const int N = N_NODES;

    // h = 0
    zero_h_kernel<<<(N_NODES * DIM / 4 + 255) / 256, 256>>>();
    // v = typed_linear(x, W_v, ntype)
    typed_gemm_kernel<<<(N + 63) / 64, 256>>>(x, W_v, ntype, v_ptr, N);
    // h[dst] += v[src]
    scatter_kernel<<<N_EDGES / 8, 256>>>(src, dst);
    // out = typed_linear(h, W_a, ntype)
    typed_gemm_kernel<<<(N + 63) / 64, 256>>>(h_ptr, W_a, ntype, out, N);
}

// round 2
// speedup vs baseline: 1.6469x; 1.6469x over previous
#include <cuda_runtime.h>

#define N_NODES 100000
#define N_EDGES 800000
#define DIM 128

// Scratch (allocation-free rule: __device__ globals)
__device__ float g_v[N_NODES * DIM];
__device__ float g_h[N_NODES * DIM];

typedef unsigned long long u64;

// packed-duplicate: (v, v) as f32x2 in a u64
__device__ __forceinline__ u64 packdup(float v) {
    u64 r;
    asm("mov.b64 %0, {%1, %1};" : "=l"(r) : "f"(v));
    return r;
}

// d = a * b + d  (SIMD on two packed f32 lanes) -> FFMA2
__device__ __forceinline__ void fma2(u64& d, u64 a, u64 b) {
    asm("fma.rn.f32x2 %0, %1, %2, %0;" : "+l"(d) : "l"(a), "l"(b));
}

// ---------------------------------------------------------------------------
// Typed GEMM: Y[n,:] = X[n,:] @ W[ntype[n]]   (W: [2,128,128] row-major)
// BM=128, BN=128, BK=16. 256 threads, 8x8 per thread via packed f32x2 FMA.
// Xs holds duplicated pairs (x,x) so the inner loop needs no packing movs.
// ntype sorted -> single-type fast path; at most one mixed block does 2 passes.
// ---------------------------------------------------------------------------
__global__ __launch_bounds__(256, 2) void typed_gemm_kernel(
    const float* __restrict__ X, const float* __restrict__ W,
    const int* __restrict__ ntype, float* __restrict__ Y, int N)
{
    __shared__ u64   Xs[16][128];   // [kk][row]  duplicated (x,x)  16KB
    __shared__ float Ws[16][128];   // [kk][col]                     8KB

    const int tx   = threadIdx.x;
    const int row0 = blockIdx.x * 128;
    const int cg   = tx & 15;   // cols cg*8 .. cg*8+7
    const int rg   = tx >> 4;   // rows rg*8 .. rg*8+7

    const int lastRow = (row0 + 127 < N) ? (row0 + 127) : (N - 1);
    const int t0 = ntype[(row0 < N) ? row0 : N - 1];
    const int t1 = ntype[lastRow];

    // loader mapping: each thread owns 8 consecutive k's of one row
    const int lr = tx >> 1;         // row 0..127
    const int lk = (tx & 1) * 8;    // k offset 0 or 8

    for (int t = t0; t <= t1; ++t) {
        const float* Wt = W + t * DIM * DIM;

        u64 acc[8][4];
        #pragma unroll
        for (int i = 0; i < 8; i++)
            #pragma unroll
            for (int p = 0; p < 4; p++) acc[i][p] = 0ull;  // (0.f,0.f)

        for (int k0 = 0; k0 < DIM; k0 += 16) {
            // --- load X tile [128 x 16] -> transposed, duplicated
            {
                const int grow = row0 + lr;
                float4 x0 = make_float4(0.f, 0.f, 0.f, 0.f);
                float4 x1 = x0;
                if (grow < N) {
                    const float* xp = X + (size_t)grow * DIM + k0 + lk;
                    x0 = *(const float4*)(xp);
                    x1 = *(const float4*)(xp + 4);
                }
                Xs[lk + 0][lr] = packdup(x0.x);
                Xs[lk + 1][lr] = packdup(x0.y);
                Xs[lk + 2][lr] = packdup(x0.z);
                Xs[lk + 3][lr] = packdup(x0.w);
                Xs[lk + 4][lr] = packdup(x1.x);
                Xs[lk + 5][lr] = packdup(x1.y);
                Xs[lk + 6][lr] = packdup(x1.z);
                Xs[lk + 7][lr] = packdup(x1.w);
            }
            // --- load W tile [16 x 128]: 512 float4 / 256 threads = 2 each
            {
                #pragma unroll
                for (int l = 0; l < 2; l++) {
                    const int f  = tx + l * 256;
                    const int kk = f >> 5;
                    const int c4 = f & 31;
                    *(float4*)(&Ws[kk][c4 * 4]) =
                        *(const float4*)(Wt + (size_t)(k0 + kk) * DIM + c4 * 4);
                }
            }
            __syncthreads();

            #pragma unroll
            for (int kk = 0; kk < 16; kk++) {
                ulonglong2 a01 = *(const ulonglong2*)(&Xs[kk][rg * 8 + 0]);
                ulonglong2 a23 = *(const ulonglong2*)(&Xs[kk][rg * 8 + 2]);
                ulonglong2 a45 = *(const ulonglong2*)(&Xs[kk][rg * 8 + 4]);
                ulonglong2 a67 = *(const ulonglong2*)(&Xs[kk][rg * 8 + 6]);
                ulonglong2 bl  = *(const ulonglong2*)(&Ws[kk][cg * 8 + 0]);
                ulonglong2 bh  = *(const ulonglong2*)(&Ws[kk][cg * 8 + 4]);
                const u64 a[8] = {a01.x, a01.y, a23.x, a23.y,
                                  a45.x, a45.y, a67.x, a67.y};
                const u64 b[4] = {bl.x, bl.y, bh.x, bh.y};
                #pragma unroll
                for (int i = 0; i < 8; i++) {
                    fma2(acc[i][0], a[i], b[0]);
                    fma2(acc[i][1], a[i], b[1]);
                    fma2(acc[i][2], a[i], b[2]);
                    fma2(acc[i][3], a[i], b[3]);
                }
            }
            __syncthreads();
        }

        // --- writeout (packed pairs map to adjacent columns, little-endian)
        const bool uniform = (t0 == t1);
        #pragma unroll
        for (int i = 0; i < 8; i++) {
            const int grow = row0 + rg * 8 + i;
            if (grow < N && (uniform || ntype[grow] == t)) {
                ulonglong2 o0, o1;
                o0.x = acc[i][0]; o0.y = acc[i][1];
                o1.x = acc[i][2]; o1.y = acc[i][3];
                *(ulonglong2*)(Y + (size_t)grow * DIM + cg * 8)     = o0;
                *(ulonglong2*)(Y + (size_t)grow * DIM + cg * 8 + 4) = o1;
            }
        }
    }
}

// ---------------------------------------------------------------------------
// Edge scatter-sum: g_h[dst[e],:] += g_v[src[e],:]. One warp per edge.
// Each lane moves one float4 with a single vector reduction (RED.128).
// ---------------------------------------------------------------------------
__global__ __launch_bounds__(256) void scatter_kernel(
    const int* __restrict__ src, const int* __restrict__ dst)
{
    const int w    = (int)((blockIdx.x * (unsigned)blockDim.x + threadIdx.x) >> 5);
    const int lane = threadIdx.x & 31;
    if (w >= N_EDGES) return;

    const int s = __ldg(src + w);
    const int d = __ldg(dst + w);

    const float4 x = ((const float4*)(g_v + (size_t)s * DIM))[lane];
    float* hd = g_h + (size_t)d * DIM + lane * 4;
    asm volatile("red.global.add.v4.f32 [%0], {%1, %2, %3, %4};"
                 :: "l"(hd), "f"(x.x), "f"(x.y), "f"(x.z), "f"(x.w)
                 : "memory");
}

// ---------------------------------------------------------------------------
__global__ __launch_bounds__(256) void zero_h_kernel()
{
    const int i = blockIdx.x * blockDim.x + threadIdx.x;
    const int total = N_NODES * DIM / 4;
    if (i < total)
        ((float4*)g_h)[i] = make_float4(0.f, 0.f, 0.f, 0.f);
}

// ---------------------------------------------------------------------------
extern "C" void kernel_launch(void* const* d_in, const int* in_sizes, int n_in,
                              void* d_out, int out_size)
{
    const float* x     = (const float*)d_in[0];
    const int*   ntype = (const int*)  d_in[1];
    const int*   src   = (const int*)  d_in[2];
    const int*   dst   = (const int*)  d_in[3];
    const float* W_v   = (const float*)d_in[4];
    const float* W_a   = (const float*)d_in[5];
    float*       out   = (float*)d_out;

    float *v_ptr, *h_ptr;
    cudaGetSymbolAddress((void**)&v_ptr, g_v);
    cudaGetSymbolAddress((void**)&h_ptr, g_h);

    const int N = N_NODES;

    // h = 0
    zero_h_kernel<<<(N_NODES * DIM / 4 + 255) / 256, 256>>>();
    // v = typed_linear(x, W_v, ntype)
    typed_gemm_kernel<<<(N + 127) / 128, 256>>>(x, W_v, ntype, v_ptr, N);
    // h[dst] += v[src]
    scatter_kernel<<<N_EDGES / 8, 256>>>(src, dst);
    // out = typed_linear(h, W_a, ntype)
    typed_gemm_kernel<<<(N + 127) / 128, 256>>>(h_ptr, W_a, ntype, out, N);
}

// round 4
// speedup vs baseline: 2.2696x; 1.3781x over previous
#include <cuda_runtime.h>
#include <cuda_bf16.h>
#include <cstdint>

#define N_NODES 100000
#define N_EDGES 800000
#define DIM 128

// ---------------------------------------------------------------------------
// Scratch (allocation-free rule: __device__ globals)
// ---------------------------------------------------------------------------
__device__ float g_v[N_NODES * DIM];
__device__ float g_h[N_NODES * DIM];
// Prepacked W: [mat*2+type][seg(0=hi,1=lo)] -> swizzled [n][k] bf16 SMEM image
// (32KB per seg image; hi followed by lo = contiguous 64KB per tile).
__device__ unsigned short g_Wmma[4][2 * 128 * 128];

// swizzled byte offset of (row, 16B-chunk kc) in a 256B-row tile
#define SW_OFF(row, kc) ((uint32_t)(row) * 256u + ((uint32_t)(((kc) ^ ((row) & 7))) << 4))

__device__ __forceinline__ uint32_t smem_u32(const void* p) {
    uint32_t a;
    asm("{ .reg .u64 t; cvta.to.shared.u64 t, %1; cvt.u32.u64 %0, t; }"
        : "=r"(a) : "l"(p));
    return a;
}
__device__ __forceinline__ void ldsm_x4(uint32_t& r0, uint32_t& r1, uint32_t& r2,
                                        uint32_t& r3, uint32_t addr) {
    asm volatile("ldmatrix.sync.aligned.m8n8.x4.shared.b16 {%0,%1,%2,%3}, [%4];"
                 : "=r"(r0), "=r"(r1), "=r"(r2), "=r"(r3) : "r"(addr));
}
__device__ __forceinline__ void mma_bf16(float* d, const uint32_t* a, const uint32_t* b) {
    asm volatile(
        "mma.sync.aligned.m16n8k16.row.col.f32.bf16.bf16.f32 "
        "{%0,%1,%2,%3}, {%4,%5,%6,%7}, {%8,%9}, {%0,%1,%2,%3};"
        : "+f"(d[0]), "+f"(d[1]), "+f"(d[2]), "+f"(d[3])
        : "r"(a[0]), "r"(a[1]), "r"(a[2]), "r"(a[3]), "r"(b[0]), "r"(b[1]));
}

// ---------------------------------------------------------------------------
// Prepack W -> g_Wmma: bf16 hi/lo, [n][k] rows (256B), XOR-swizzled 16B chunks
// W layout: [type][k][n] row-major (d_in x d_out)
// ---------------------------------------------------------------------------
__global__ __launch_bounds__(256) void prepack_kernel(
    const float* __restrict__ W_v, const float* __restrict__ W_a)
{
    const int idx = blockIdx.x * 256 + threadIdx.x;   // 4*2*16384 total
    if (idx >= 4 * 2 * 128 * 128) return;
    const int tile = idx >> 15;            // 0..3 (mat,type)
    const int seg  = (idx >> 14) & 1;      // 0=hi, 1=lo
    const int rem  = idx & 16383;
    const int n    = rem >> 7;             // 0..127
    const int k    = rem & 127;            // 0..127
    const int mat  = tile >> 1;
    const int typ  = tile & 1;

    const float* Wp = (mat ? W_a : W_v) + typ * DIM * DIM;
    const float w = Wp[k * DIM + n];
    __nv_bfloat16 hi = __float2bfloat16_rn(w);
    unsigned short out;
    if (seg == 0) {
        out = *(unsigned short*)&hi;
    } else {
        __nv_bfloat16 lo = __float2bfloat16_rn(w - __bfloat162float(hi));
        out = *(unsigned short*)&lo;
    }
    const uint32_t boff = SW_OFF(n, k >> 3) + (k & 7) * 2;
    g_Wmma[tile][seg * 16384 + (boff >> 1)] = out;
}

// ---------------------------------------------------------------------------
// Typed tensor-core GEMM (mma.sync bf16, hi/lo split): Y = X @ W[ntype]
// CTA: 128 rows x 128 cols, 256 threads (8 warps: 4(m) x 2(n) grid, each
// warp 32x64). SMEM: Xhi|Xlo|Whi|Wlo, 32KB each, swizzled 256B rows.
// ntype sorted -> single-type fast path; mixed block does 2 masked passes.
// ---------------------------------------------------------------------------
__global__ __launch_bounds__(256) void gemm_mma_kernel(
    const float* __restrict__ X, int mat,
    const int* __restrict__ ntype, float* __restrict__ Y, int N)
{
    extern __shared__ char dsm[];
    const uint32_t sbase = smem_u32(dsm);
    const uint32_t XH = 0, XL = 32768, WH = 65536;

    const int tid  = threadIdx.x;
    const int wid  = tid >> 5;
    const int lane = tid & 31;
    const int row0 = blockIdx.x * 128;

    const int lastRow = (row0 + 127 < N) ? (row0 + 127) : (N - 1);
    const int t0 = ntype[row0];
    const int t1 = ntype[lastRow];
    const bool mixed = (t0 != t1);

    // ---- convert X fp32 -> bf16 hi/lo into swizzled SMEM (done once) ------
    {
        const int row  = tid >> 1;            // 0..127
        const int kh   = (tid & 1) * 8;       // chunk base 0 or 8
        const int grow = row0 + row;
        const float4* xp = (const float4*)(X + (size_t)grow * DIM + kh * 8);
        #pragma unroll
        for (int q = 0; q < 8; q++) {
            float4 f0, f1;
            if (grow < N) { f0 = xp[2 * q]; f1 = xp[2 * q + 1]; }
            else { f0 = make_float4(0, 0, 0, 0); f1 = f0; }
            __nv_bfloat162 h0 = __floats2bfloat162_rn(f0.x, f0.y);
            __nv_bfloat162 h1 = __floats2bfloat162_rn(f0.z, f0.w);
            __nv_bfloat162 h2 = __floats2bfloat162_rn(f1.x, f1.y);
            __nv_bfloat162 h3 = __floats2bfloat162_rn(f1.z, f1.w);
            float2 e0 = __bfloat1622float2(h0), e1 = __bfloat1622float2(h1);
            float2 e2 = __bfloat1622float2(h2), e3 = __bfloat1622float2(h3);
            __nv_bfloat162 l0 = __floats2bfloat162_rn(f0.x - e0.x, f0.y - e0.y);
            __nv_bfloat162 l1 = __floats2bfloat162_rn(f0.z - e1.x, f0.w - e1.y);
            __nv_bfloat162 l2 = __floats2bfloat162_rn(f1.x - e2.x, f1.y - e2.y);
            __nv_bfloat162 l3 = __floats2bfloat162_rn(f1.z - e3.x, f1.w - e3.y);
            const uint32_t off = SW_OFF(row, kh + q);
            uint4 hv, lv;
            hv.x = *(uint32_t*)&h0; hv.y = *(uint32_t*)&h1;
            hv.z = *(uint32_t*)&h2; hv.w = *(uint32_t*)&h3;
            lv.x = *(uint32_t*)&l0; lv.y = *(uint32_t*)&l1;
            lv.z = *(uint32_t*)&l2; lv.w = *(uint32_t*)&l3;
            *(uint4*)(dsm + XH + off) = hv;
            *(uint4*)(dsm + XL + off) = lv;
        }
    }

    // warp tile position
    const int m0 = (wid >> 1) * 32;
    const int n0 = (wid & 1) * 64;

    for (int t = t0; t <= t1; ++t) {
        __syncthreads();
        // ---- copy prepacked W (hi+lo, 64KB) into SMEM ----------------------
        {
            const uint4* srcW = (const uint4*)g_Wmma[mat * 2 + t];
            uint4* dstW = (uint4*)(dsm + WH);
            #pragma unroll
            for (int i = 0; i < 16; i++)
                dstW[tid + 256 * i] = srcW[tid + 256 * i];
        }
        __syncthreads();

        float acc[2][8][4];
        #pragma unroll
        for (int i = 0; i < 2; i++)
            #pragma unroll
            for (int j = 0; j < 8; j++)
                #pragma unroll
                for (int p = 0; p < 4; p++) acc[i][j][p] = 0.f;

        // 3 segments: (Xhi,Whi), (Xlo,Whi), (Xhi,Wlo)
        #pragma unroll
        for (int seg = 0; seg < 3; seg++) {
            const uint32_t abase = sbase + ((seg == 1) ? XL : XH);
            const uint32_t bbase = sbase + WH + ((seg == 2) ? 32768u : 0u);
            #pragma unroll
            for (int ks = 0; ks < 8; ks++) {
                uint32_t a[2][4];
                {
                    const int r    = lane & 7;
                    const int half = (lane >> 3) & 1;
                    const int ksel = lane >> 4;
                    const int akc  = ks * 2 + ksel;
                    #pragma unroll
                    for (int mt = 0; mt < 2; mt++) {
                        const int arow = m0 + mt * 16 + half * 8 + r;
                        ldsm_x4(a[mt][0], a[mt][1], a[mt][2], a[mt][3],
                                abase + SW_OFF(arow, akc));
                    }
                }
                uint32_t b[8][2];
                {
                    const int r    = lane & 7;
                    const int ksel = (lane >> 3) & 1;
                    const int jsel = lane >> 4;
                    const int bkc  = ks * 2 + ksel;
                    #pragma unroll
                    for (int jj = 0; jj < 4; jj++) {
                        const int brow = n0 + jj * 16 + jsel * 8 + r;
                        uint32_t r0, r1, r2, r3;
                        ldsm_x4(r0, r1, r2, r3, bbase + SW_OFF(brow, bkc));
                        b[2 * jj][0] = r0;     b[2 * jj][1] = r1;
                        b[2 * jj + 1][0] = r2; b[2 * jj + 1][1] = r3;
                    }
                }
                #pragma unroll
                for (int mt = 0; mt < 2; mt++)
                    #pragma unroll
                    for (int nt = 0; nt < 8; nt++)
                        mma_bf16(acc[mt][nt], a[mt], b[nt]);
            }
        }

        // ---- epilogue: masked writeout ------------------------------------
        {
            const int g  = lane >> 2;
            const int c2 = (lane & 3) * 2;
            #pragma unroll
            for (int mt = 0; mt < 2; mt++) {
                #pragma unroll
                for (int half = 0; half < 2; half++) {
                    const int grow = row0 + m0 + mt * 16 + half * 8 + g;
                    if (grow < N && (!mixed || ntype[grow] == t)) {
                        float2* yp = (float2*)(Y + (size_t)grow * DIM + n0 + c2);
                        #pragma unroll
                        for (int nt = 0; nt < 8; nt++)
                            yp[nt * 4] = make_float2(acc[mt][nt][half * 2],
                                                     acc[mt][nt][half * 2 + 1]);
                    }
                }
            }
        }
    }
}

// ---------------------------------------------------------------------------
// Edge scatter-sum: g_h[dst[e],:] += g_v[src[e],:]. Warp/edge, RED.128/lane.
// ---------------------------------------------------------------------------
__global__ __launch_bounds__(256) void scatter_kernel(
    const int* __restrict__ src, const int* __restrict__ dst)
{
    const int w    = (int)((blockIdx.x * (unsigned)blockDim.x + threadIdx.x) >> 5);
    const int lane = threadIdx.x & 31;
    if (w >= N_EDGES) return;

    const int s = __ldg(src + w);
    const int d = __ldg(dst + w);

    const float4 x = ((const float4*)(g_v + (size_t)s * DIM))[lane];
    float* hd = g_h + (size_t)d * DIM + lane * 4;
    asm volatile("red.global.add.v4.f32 [%0], {%1, %2, %3, %4};"
                 :: "l"(hd), "f"(x.x), "f"(x.y), "f"(x.z), "f"(x.w)
                 : "memory");
}

// ---------------------------------------------------------------------------
__global__ __launch_bounds__(256) void zero_h_kernel()
{
    const int i = blockIdx.x * blockDim.x + threadIdx.x;
    if (i < N_NODES * DIM / 4)
        ((float4*)g_h)[i] = make_float4(0.f, 0.f, 0.f, 0.f);
}

// ---------------------------------------------------------------------------
extern "C" void kernel_launch(void* const* d_in, const int* in_sizes, int n_in,
                              void* d_out, int out_size)
{
    const float* x     = (const float*)d_in[0];
    const int*   ntype = (const int*)  d_in[1];
    const int*   src   = (const int*)  d_in[2];
    const int*   dst   = (const int*)  d_in[3];
    const float* W_v   = (const float*)d_in[4];
    const float* W_a   = (const float*)d_in[5];
    float*       out   = (float*)d_out;

    float *v_ptr, *h_ptr;
    cudaGetSymbolAddress((void**)&v_ptr, g_v);
    cudaGetSymbolAddress((void**)&h_ptr, g_h);

    const int N = N_NODES;
    const int SMEM_DYN = 131072;   // Xhi+Xlo+Whi+Wlo
    cudaFuncSetAttribute(gemm_mma_kernel,
                         cudaFuncAttributeMaxDynamicSharedMemorySize, SMEM_DYN);

    // prepack W (bf16 hi/lo swizzled SMEM images)
    prepack_kernel<<<(4 * 2 * 128 * 128 + 255) / 256, 256>>>(W_v, W_a);
    // h = 0
    zero_h_kernel<<<(N_NODES * DIM / 4 + 255) / 256, 256>>>();
    // v = typed_linear(x, W_v, ntype)
    gemm_mma_kernel<<<(N + 127) / 128, 256, SMEM_DYN>>>(x, 0, ntype, v_ptr, N);
    // h[dst] += v[src]
    scatter_kernel<<<N_EDGES / 8, 256>>>(src, dst);
    // out = typed_linear(h, W_a, ntype)
    gemm_mma_kernel<<<(N + 127) / 128, 256, SMEM_DYN>>>(h_ptr, 1, ntype, out, N);
}

// round 5
// speedup vs baseline: 2.4389x; 1.0746x over previous
#include <cuda_runtime.h>
#include <cuda_bf16.h>
#include <cstdint>

#define N_NODES 100000
#define N_EDGES 800000
#define DIM 128
#define NTILES ((N_NODES + 127) / 128)

// ---------------------------------------------------------------------------
// Scratch (allocation-free rule: __device__ globals)
// ---------------------------------------------------------------------------
__device__ float g_v[N_NODES * DIM];
__device__ float g_h[N_NODES * DIM];
// Prepacked W: [mat*2+type] -> (hi 32KB | lo 32KB) swizzled [n][k] bf16 image
__device__ unsigned short g_Wmma[4][2 * 128 * 128];

// swizzled byte offset of (row, 16B-chunk kc) in a 256B-row tile
#define SW_OFF(row, kc) ((uint32_t)(row) * 256u + ((uint32_t)(((kc) ^ ((row) & 7))) << 4))

__device__ __forceinline__ uint32_t smem_u32(const void* p) {
    uint32_t a;
    asm("{ .reg .u64 t; cvta.to.shared.u64 t, %1; cvt.u32.u64 %0, t; }"
        : "=r"(a) : "l"(p));
    return a;
}
__device__ __forceinline__ void ldsm_x4(uint32_t& r0, uint32_t& r1, uint32_t& r2,
                                        uint32_t& r3, uint32_t addr) {
    asm volatile("ldmatrix.sync.aligned.m8n8.x4.shared.b16 {%0,%1,%2,%3}, [%4];"
                 : "=r"(r0), "=r"(r1), "=r"(r2), "=r"(r3) : "r"(addr));
}
__device__ __forceinline__ void mma_bf16(float* d, const uint32_t* a, const uint32_t* b) {
    asm volatile(
        "mma.sync.aligned.m16n8k16.row.col.f32.bf16.bf16.f32 "
        "{%0,%1,%2,%3}, {%4,%5,%6,%7}, {%8,%9}, {%0,%1,%2,%3};"
        : "+f"(d[0]), "+f"(d[1]), "+f"(d[2]), "+f"(d[3])
        : "r"(a[0]), "r"(a[1]), "r"(a[2]), "r"(a[3]), "r"(b[0]), "r"(b[1]));
}

// ---------------------------------------------------------------------------
// Prepack W -> g_Wmma: bf16 hi/lo, [n][k] rows (256B), XOR-swizzled 16B chunks
// ---------------------------------------------------------------------------
__global__ __launch_bounds__(256) void prepack_kernel(
    const float* __restrict__ W_v, const float* __restrict__ W_a)
{
    const int idx = blockIdx.x * 256 + threadIdx.x;   // 4*2*16384 total
    if (idx >= 4 * 2 * 128 * 128) return;
    const int tile = idx >> 15;            // 0..3 (mat,type)
    const int seg  = (idx >> 14) & 1;      // 0=hi, 1=lo
    const int rem  = idx & 16383;
    const int n    = rem >> 7;             // 0..127
    const int k    = rem & 127;            // 0..127
    const int mat  = tile >> 1;
    const int typ  = tile & 1;

    const float* Wp = (mat ? W_a : W_v) + typ * DIM * DIM;
    const float w = Wp[k * DIM + n];
    __nv_bfloat16 hi = __float2bfloat16_rn(w);
    unsigned short out;
    if (seg == 0) {
        out = *(unsigned short*)&hi;
    } else {
        __nv_bfloat16 lo = __float2bfloat16_rn(w - __bfloat162float(hi));
        out = *(unsigned short*)&lo;
    }
    const uint32_t boff = SW_OFF(n, k >> 3) + (k & 7) * 2;
    g_Wmma[tile][seg * 16384 + (boff >> 1)] = out;
}

// ---------------------------------------------------------------------------
// Persistent typed tensor-core GEMM: Y = X @ W[ntype]
// grid = 148 CTAs, 256 threads. W (both types, hi/lo = 128KB) loaded ONCE
// into SMEM; CTA grid-strides over 128-row tiles. Inner loop loads all 4
// fragment sets per k-step once and issues 3 MMA combos (hi*hi+lo*hi+hi*lo).
// SMEM: Xhi(32K)|Xlo(32K)|W[t0](64K)|W[t1](64K) = 192KB.
// ---------------------------------------------------------------------------
__global__ __launch_bounds__(256) void gemm_mma_kernel(
    const float* __restrict__ X, int mat,
    const int* __restrict__ ntype, float* __restrict__ Y, int N)
{
    extern __shared__ char dsm[];
    const uint32_t sbase = smem_u32(dsm);
    const uint32_t XH = 0, XL = 32768, WB = 65536;   // W: +type*65536 +seg*32768

    const int tid  = threadIdx.x;
    const int wid  = tid >> 5;
    const int lane = tid & 31;

    // ---- load W (both types, hi+lo = 128KB) once -------------------------
    {
        const uint4* srcW0 = (const uint4*)g_Wmma[mat * 2 + 0];
        const uint4* srcW1 = (const uint4*)g_Wmma[mat * 2 + 1];
        uint4* dstW0 = (uint4*)(dsm + WB);
        uint4* dstW1 = (uint4*)(dsm + WB + 65536);
        #pragma unroll
        for (int i = 0; i < 16; i++) {
            dstW0[tid + 256 * i] = srcW0[tid + 256 * i];
            dstW1[tid + 256 * i] = srcW1[tid + 256 * i];
        }
    }

    // warp tile position (4m x 2n grid of 32x64 warp tiles)
    const int m0 = (wid >> 1) * 32;
    const int n0 = (wid & 1) * 64;

    for (int tile = blockIdx.x; tile < NTILES; tile += gridDim.x) {
        const int row0 = tile * 128;
        const int lastRow = (row0 + 127 < N) ? (row0 + 127) : (N - 1);
        const int t0 = ntype[row0];
        const int t1 = ntype[lastRow];
        const bool mixed = (t0 != t1);

        __syncthreads();   // previous tile's compute done before X overwrite

        // ---- convert X fp32 -> bf16 hi/lo into swizzled SMEM -------------
        {
            const int row  = tid >> 1;            // 0..127
            const int kh   = (tid & 1) * 8;       // chunk base 0 or 8
            const int grow = row0 + row;
            const float4* xp = (const float4*)(X + (size_t)grow * DIM + kh * 8);
            #pragma unroll
            for (int q = 0; q < 8; q++) {
                float4 f0, f1;
                if (grow < N) { f0 = xp[2 * q]; f1 = xp[2 * q + 1]; }
                else { f0 = make_float4(0, 0, 0, 0); f1 = f0; }
                __nv_bfloat162 h0 = __floats2bfloat162_rn(f0.x, f0.y);
                __nv_bfloat162 h1 = __floats2bfloat162_rn(f0.z, f0.w);
                __nv_bfloat162 h2 = __floats2bfloat162_rn(f1.x, f1.y);
                __nv_bfloat162 h3 = __floats2bfloat162_rn(f1.z, f1.w);
                float2 e0 = __bfloat1622float2(h0), e1 = __bfloat1622float2(h1);
                float2 e2 = __bfloat1622float2(h2), e3 = __bfloat1622float2(h3);
                __nv_bfloat162 l0 = __floats2bfloat162_rn(f0.x - e0.x, f0.y - e0.y);
                __nv_bfloat162 l1 = __floats2bfloat162_rn(f0.z - e1.x, f0.w - e1.y);
                __nv_bfloat162 l2 = __floats2bfloat162_rn(f1.x - e2.x, f1.y - e2.y);
                __nv_bfloat162 l3 = __floats2bfloat162_rn(f1.z - e3.x, f1.w - e3.y);
                const uint32_t off = SW_OFF(row, kh + q);
                uint4 hv, lv;
                hv.x = *(uint32_t*)&h0; hv.y = *(uint32_t*)&h1;
                hv.z = *(uint32_t*)&h2; hv.w = *(uint32_t*)&h3;
                lv.x = *(uint32_t*)&l0; lv.y = *(uint32_t*)&l1;
                lv.z = *(uint32_t*)&l2; lv.w = *(uint32_t*)&l3;
                *(uint4*)(dsm + XH + off) = hv;
                *(uint4*)(dsm + XL + off) = lv;
            }
        }
        __syncthreads();

        for (int t = t0; t <= t1; ++t) {
            const uint32_t bhi = sbase + WB + (uint32_t)t * 65536u;
            const uint32_t blo = bhi + 32768u;

            float acc[2][8][4];
            #pragma unroll
            for (int i = 0; i < 2; i++)
                #pragma unroll
                for (int j = 0; j < 8; j++)
                    #pragma unroll
                    for (int p = 0; p < 4; p++) acc[i][j][p] = 0.f;

            #pragma unroll
            for (int ks = 0; ks < 8; ks++) {
                // ---- A fragments (hi & lo) --------------------------------
                uint32_t ah[2][4], al[2][4];
                {
                    const int r    = lane & 7;
                    const int half = (lane >> 3) & 1;
                    const int ksel = lane >> 4;
                    const int akc  = ks * 2 + ksel;
                    #pragma unroll
                    for (int mt = 0; mt < 2; mt++) {
                        const uint32_t aoff = SW_OFF(m0 + mt * 16 + half * 8 + r, akc);
                        ldsm_x4(ah[mt][0], ah[mt][1], ah[mt][2], ah[mt][3],
                                sbase + XH + aoff);
                        ldsm_x4(al[mt][0], al[mt][1], al[mt][2], al[mt][3],
                                sbase + XL + aoff);
                    }
                }
                // ---- B fragments (hi & lo) --------------------------------
                uint32_t bh[8][2], bl[8][2];
                {
                    const int r    = lane & 7;
                    const int ksel = (lane >> 3) & 1;
                    const int jsel = lane >> 4;
                    const int bkc  = ks * 2 + ksel;
                    #pragma unroll
                    for (int jj = 0; jj < 4; jj++) {
                        const uint32_t boff = SW_OFF(n0 + jj * 16 + jsel * 8 + r, bkc);
                        uint32_t r0, r1, r2, r3;
                        ldsm_x4(r0, r1, r2, r3, bhi + boff);
                        bh[2 * jj][0] = r0;     bh[2 * jj][1] = r1;
                        bh[2 * jj + 1][0] = r2; bh[2 * jj + 1][1] = r3;
                        ldsm_x4(r0, r1, r2, r3, blo + boff);
                        bl[2 * jj][0] = r0;     bl[2 * jj][1] = r1;
                        bl[2 * jj + 1][0] = r2; bl[2 * jj + 1][1] = r3;
                    }
                }
                // ---- 3 MMA combos from registers --------------------------
                #pragma unroll
                for (int mt = 0; mt < 2; mt++)
                    #pragma unroll
                    for (int nt = 0; nt < 8; nt++) {
                        mma_bf16(acc[mt][nt], ah[mt], bh[nt]);
                        mma_bf16(acc[mt][nt], al[mt], bh[nt]);
                        mma_bf16(acc[mt][nt], ah[mt], bl[nt]);
                    }
            }

            // ---- epilogue: masked writeout --------------------------------
            {
                const int g  = lane >> 2;
                const int c2 = (lane & 3) * 2;
                #pragma unroll
                for (int mt = 0; mt < 2; mt++) {
                    #pragma unroll
                    for (int half = 0; half < 2; half++) {
                        const int grow = row0 + m0 + mt * 16 + half * 8 + g;
                        if (grow < N && (!mixed || ntype[grow] == t)) {
                            float2* yp = (float2*)(Y + (size_t)grow * DIM + n0 + c2);
                            #pragma unroll
                            for (int nt = 0; nt < 8; nt++)
                                yp[nt * 4] = make_float2(acc[mt][nt][half * 2],
                                                         acc[mt][nt][half * 2 + 1]);
                        }
                    }
                }
            }
        }
    }
}

// ---------------------------------------------------------------------------
// Edge scatter-sum: g_h[dst[e],:] += g_v[src[e],:]. Warp/edge, RED.128/lane.
// ---------------------------------------------------------------------------
__global__ __launch_bounds__(256) void scatter_kernel(
    const int* __restrict__ src, const int* __restrict__ dst)
{
    const int w    = (int)((blockIdx.x * (unsigned)blockDim.x + threadIdx.x) >> 5);
    const int lane = threadIdx.x & 31;
    if (w >= N_EDGES) return;

    const int s = __ldg(src + w);
    const int d = __ldg(dst + w);

    const float4 x = ((const float4*)(g_v + (size_t)s * DIM))[lane];
    float* hd = g_h + (size_t)d * DIM + lane * 4;
    asm volatile("red.global.add.v4.f32 [%0], {%1, %2, %3, %4};"
                 :: "l"(hd), "f"(x.x), "f"(x.y), "f"(x.z), "f"(x.w)
                 : "memory");
}

// ---------------------------------------------------------------------------
__global__ __launch_bounds__(256) void zero_h_kernel()
{
    const int i = blockIdx.x * blockDim.x + threadIdx.x;
    if (i < N_NODES * DIM / 4)
        ((float4*)g_h)[i] = make_float4(0.f, 0.f, 0.f, 0.f);
}

// ---------------------------------------------------------------------------
extern "C" void kernel_launch(void* const* d_in, const int* in_sizes, int n_in,
                              void* d_out, int out_size)
{
    const float* x     = (const float*)d_in[0];
    const int*   ntype = (const int*)  d_in[1];
    const int*   src   = (const int*)  d_in[2];
    const int*   dst   = (const int*)  d_in[3];
    const float* W_v   = (const float*)d_in[4];
    const float* W_a   = (const float*)d_in[5];
    float*       out   = (float*)d_out;

    float *v_ptr, *h_ptr;
    cudaGetSymbolAddress((void**)&v_ptr, g_v);
    cudaGetSymbolAddress((void**)&h_ptr, g_h);

    const int N = N_NODES;
    const int SMEM_DYN = 196608;   // Xhi+Xlo (64K) + W both types hi/lo (128K)
    cudaFuncSetAttribute(gemm_mma_kernel,
                         cudaFuncAttributeMaxDynamicSharedMemorySize, SMEM_DYN);

    // prepack W (bf16 hi/lo swizzled SMEM images)
    prepack_kernel<<<(4 * 2 * 128 * 128 + 255) / 256, 256>>>(W_v, W_a);
    // h = 0
    zero_h_kernel<<<(N_NODES * DIM / 4 + 255) / 256, 256>>>();
    // v = typed_linear(x, W_v, ntype)
    gemm_mma_kernel<<<148, 256, SMEM_DYN>>>(x, 0, ntype, v_ptr, N);
    // h[dst] += v[src]
    scatter_kernel<<<N_EDGES / 8, 256>>>(src, dst);
    // out = typed_linear(h, W_a, ntype)
    gemm_mma_kernel<<<148, 256, SMEM_DYN>>>(h_ptr, 1, ntype, out, N);
}

// round 6
// speedup vs baseline: 3.0681x; 1.2580x over previous
#include <cuda_runtime.h>
#include <cuda_bf16.h>
#include <cstdint>

#define N_NODES 100000
#define N_EDGES 800000
#define DIM 128
#define NTILES ((N_NODES + 127) / 128)

// ---------------------------------------------------------------------------
// Scratch (allocation-free rule: __device__ globals)
// ---------------------------------------------------------------------------
__device__ float g_v[N_NODES * DIM];
__device__ float g_h[N_NODES * DIM];
// Prepacked W: [mat*2+type] -> (hi 32KB | lo 32KB) swizzled [n][k] bf16 image
__device__ unsigned short g_Wmma[4][2 * 128 * 128];

// swizzled byte offset of (row, 16B-chunk kc) in a 256B-row tile
#define SW_OFF(row, kc) ((uint32_t)(row) * 256u + ((uint32_t)(((kc) ^ ((row) & 7))) << 4))

__device__ __forceinline__ uint32_t smem_u32(const void* p) {
    uint32_t a;
    asm("{ .reg .u64 t; cvta.to.shared.u64 t, %1; cvt.u32.u64 %0, t; }"
        : "=r"(a) : "l"(p));
    return a;
}
__device__ __forceinline__ void ldsm_x4(uint32_t& r0, uint32_t& r1, uint32_t& r2,
                                        uint32_t& r3, uint32_t addr) {
    asm volatile("ldmatrix.sync.aligned.m8n8.x4.shared.b16 {%0,%1,%2,%3}, [%4];"
                 : "=r"(r0), "=r"(r1), "=r"(r2), "=r"(r3) : "r"(addr));
}
__device__ __forceinline__ void mma_bf16(float* d, const uint32_t* a, const uint32_t* b) {
    asm volatile(
        "mma.sync.aligned.m16n8k16.row.col.f32.bf16.bf16.f32 "
        "{%0,%1,%2,%3}, {%4,%5,%6,%7}, {%8,%9}, {%0,%1,%2,%3};"
        : "+f"(d[0]), "+f"(d[1]), "+f"(d[2]), "+f"(d[3])
        : "r"(a[0]), "r"(a[1]), "r"(a[2]), "r"(a[3]), "r"(b[0]), "r"(b[1]));
}

// ---------------------------------------------------------------------------
// Prepack W -> g_Wmma: bf16 hi/lo, [n][k] rows (256B), XOR-swizzled 16B chunks
// ---------------------------------------------------------------------------
__global__ __launch_bounds__(256) void prepack_kernel(
    const float* __restrict__ W_v, const float* __restrict__ W_a)
{
    const int idx = blockIdx.x * 256 + threadIdx.x;   // 4*2*16384 total
    if (idx >= 4 * 2 * 128 * 128) return;
    const int tile = idx >> 15;            // 0..3 (mat,type)
    const int seg  = (idx >> 14) & 1;      // 0=hi, 1=lo
    const int rem  = idx & 16383;
    const int n    = rem >> 7;             // 0..127
    const int k    = rem & 127;            // 0..127
    const int mat  = tile >> 1;
    const int typ  = tile & 1;

    const float* Wp = (mat ? W_a : W_v) + typ * DIM * DIM;
    const float w = Wp[k * DIM + n];
    __nv_bfloat16 hi = __float2bfloat16_rn(w);
    unsigned short out;
    if (seg == 0) {
        out = *(unsigned short*)&hi;
    } else {
        __nv_bfloat16 lo = __float2bfloat16_rn(w - __bfloat162float(hi));
        out = *(unsigned short*)&lo;
    }
    const uint32_t boff = SW_OFF(n, k >> 3) + (k & 7) * 2;
    g_Wmma[tile][seg * 16384 + (boff >> 1)] = out;
}

// ---------------------------------------------------------------------------
// Persistent typed tensor-core GEMM with X prefetch pipeline: Y = X @ W[ntype]
// grid = 148 CTAs, 256 threads. W (both types, hi/lo = 128KB) resident in
// SMEM. Per tile: convert prefetched regs -> smem, issue next tile's global
// loads (hidden behind MMA), compute 3-segment bf16 MMA, masked epilogue.
// ---------------------------------------------------------------------------
__global__ __launch_bounds__(256) void gemm_mma_kernel(
    const float* __restrict__ X, int mat,
    const int* __restrict__ ntype, float* __restrict__ Y, int N)
{
    extern __shared__ char dsm[];
    const uint32_t sbase = smem_u32(dsm);
    const uint32_t XH = 0, XL = 32768, WB = 65536;   // W: +type*65536 +seg*32768

    const int tid  = threadIdx.x;
    const int wid  = tid >> 5;
    const int lane = tid & 31;

    // ---- load W (both types, hi+lo = 128KB) once -------------------------
    {
        const uint4* srcW0 = (const uint4*)g_Wmma[mat * 2 + 0];
        const uint4* srcW1 = (const uint4*)g_Wmma[mat * 2 + 1];
        uint4* dstW0 = (uint4*)(dsm + WB);
        uint4* dstW1 = (uint4*)(dsm + WB + 65536);
        #pragma unroll
        for (int i = 0; i < 16; i++) {
            dstW0[tid + 256 * i] = srcW0[tid + 256 * i];
            dstW1[tid + 256 * i] = srcW1[tid + 256 * i];
        }
    }

    // warp tile position (4m x 2n grid of 32x64 warp tiles)
    const int m0 = (wid >> 1) * 32;
    const int n0 = (wid & 1) * 64;

    // loader mapping: row = tid>>1, k-half = (tid&1)*64 floats
    const int lrow  = tid >> 1;
    const int lkoff = (tid & 1) * 64;

    // ---- prologue: prefetch first tile's X slice into registers -----------
    float4 pf[16];
    int tile = blockIdx.x;
    {
        const int grow = tile * 128 + lrow;
        if (tile < NTILES && grow < N) {
            const float4* xp = (const float4*)(X + (size_t)grow * DIM + lkoff);
            #pragma unroll
            for (int q = 0; q < 16; q++) pf[q] = xp[q];
        } else {
            #pragma unroll
            for (int q = 0; q < 16; q++) pf[q] = make_float4(0, 0, 0, 0);
        }
    }

    while (tile < NTILES) {
        const int row0 = tile * 128;
        const int lastRow = (row0 + 127 < N) ? (row0 + 127) : (N - 1);
        const int t0 = ntype[row0];
        const int t1 = ntype[lastRow];
        const bool mixed = (t0 != t1);
        const int ntile = tile + gridDim.x;

        __syncthreads();   // previous tile's compute done before X overwrite

        // ---- convert prefetched X -> bf16 hi/lo swizzled SMEM -------------
        {
            const int kh = (tid & 1) * 8;  // 16B-chunk base
            #pragma unroll
            for (int q = 0; q < 8; q++) {
                float4 f0 = pf[2 * q], f1 = pf[2 * q + 1];
                __nv_bfloat162 h0 = __floats2bfloat162_rn(f0.x, f0.y);
                __nv_bfloat162 h1 = __floats2bfloat162_rn(f0.z, f0.w);
                __nv_bfloat162 h2 = __floats2bfloat162_rn(f1.x, f1.y);
                __nv_bfloat162 h3 = __floats2bfloat162_rn(f1.z, f1.w);
                float2 e0 = __bfloat1622float2(h0), e1 = __bfloat1622float2(h1);
                float2 e2 = __bfloat1622float2(h2), e3 = __bfloat1622float2(h3);
                __nv_bfloat162 l0 = __floats2bfloat162_rn(f0.x - e0.x, f0.y - e0.y);
                __nv_bfloat162 l1 = __floats2bfloat162_rn(f0.z - e1.x, f0.w - e1.y);
                __nv_bfloat162 l2 = __floats2bfloat162_rn(f1.x - e2.x, f1.y - e2.y);
                __nv_bfloat162 l3 = __floats2bfloat162_rn(f1.z - e3.x, f1.w - e3.y);
                const uint32_t off = SW_OFF(lrow, kh + q);
                uint4 hv, lv;
                hv.x = *(uint32_t*)&h0; hv.y = *(uint32_t*)&h1;
                hv.z = *(uint32_t*)&h2; hv.w = *(uint32_t*)&h3;
                lv.x = *(uint32_t*)&l0; lv.y = *(uint32_t*)&l1;
                lv.z = *(uint32_t*)&l2; lv.w = *(uint32_t*)&l3;
                *(uint4*)(dsm + XH + off) = hv;
                *(uint4*)(dsm + XL + off) = lv;
            }
        }

        // ---- prefetch next tile's X (latency hidden behind MMA) ----------
        {
            const int grow = ntile * 128 + lrow;
            if (ntile < NTILES && grow < N) {
                const float4* xp = (const float4*)(X + (size_t)grow * DIM + lkoff);
                #pragma unroll
                for (int q = 0; q < 16; q++) pf[q] = xp[q];
            } else {
                #pragma unroll
                for (int q = 0; q < 16; q++) pf[q] = make_float4(0, 0, 0, 0);
            }
        }
        __syncthreads();

        for (int t = t0; t <= t1; ++t) {
            const uint32_t bhi = sbase + WB + (uint32_t)t * 65536u;
            const uint32_t blo = bhi + 32768u;

            float acc[2][8][4];
            #pragma unroll
            for (int i = 0; i < 2; i++)
                #pragma unroll
                for (int j = 0; j < 8; j++)
                    #pragma unroll
                    for (int p = 0; p < 4; p++) acc[i][j][p] = 0.f;

            #pragma unroll
            for (int ks = 0; ks < 8; ks++) {
                // ---- A fragments (hi & lo) --------------------------------
                uint32_t ah[2][4], al[2][4];
                {
                    const int r    = lane & 7;
                    const int half = (lane >> 3) & 1;
                    const int ksel = lane >> 4;
                    const int akc  = ks * 2 + ksel;
                    #pragma unroll
                    for (int mt = 0; mt < 2; mt++) {
                        const uint32_t aoff = SW_OFF(m0 + mt * 16 + half * 8 + r, akc);
                        ldsm_x4(ah[mt][0], ah[mt][1], ah[mt][2], ah[mt][3],
                                sbase + XH + aoff);
                        ldsm_x4(al[mt][0], al[mt][1], al[mt][2], al[mt][3],
                                sbase + XL + aoff);
                    }
                }
                // ---- B fragments (hi & lo) --------------------------------
                uint32_t bh[8][2], bl[8][2];
                {
                    const int r    = lane & 7;
                    const int ksel = (lane >> 3) & 1;
                    const int jsel = lane >> 4;
                    const int bkc  = ks * 2 + ksel;
                    #pragma unroll
                    for (int jj = 0; jj < 4; jj++) {
                        const uint32_t boff = SW_OFF(n0 + jj * 16 + jsel * 8 + r, bkc);
                        uint32_t r0, r1, r2, r3;
                        ldsm_x4(r0, r1, r2, r3, bhi + boff);
                        bh[2 * jj][0] = r0;     bh[2 * jj][1] = r1;
                        bh[2 * jj + 1][0] = r2; bh[2 * jj + 1][1] = r3;
                        ldsm_x4(r0, r1, r2, r3, blo + boff);
                        bl[2 * jj][0] = r0;     bl[2 * jj][1] = r1;
                        bl[2 * jj + 1][0] = r2; bl[2 * jj + 1][1] = r3;
                    }
                }
                // ---- 3 MMA combos from registers --------------------------
                #pragma unroll
                for (int mt = 0; mt < 2; mt++)
                    #pragma unroll
                    for (int nt = 0; nt < 8; nt++) {
                        mma_bf16(acc[mt][nt], ah[mt], bh[nt]);
                        mma_bf16(acc[mt][nt], al[mt], bh[nt]);
                        mma_bf16(acc[mt][nt], ah[mt], bl[nt]);
                    }
            }

            // ---- epilogue: masked writeout --------------------------------
            {
                const int g  = lane >> 2;
                const int c2 = (lane & 3) * 2;
                #pragma unroll
                for (int mt = 0; mt < 2; mt++) {
                    #pragma unroll
                    for (int half = 0; half < 2; half++) {
                        const int grow = row0 + m0 + mt * 16 + half * 8 + g;
                        if (grow < N && (!mixed || ntype[grow] == t)) {
                            float2* yp = (float2*)(Y + (size_t)grow * DIM + n0 + c2);
                            #pragma unroll
                            for (int nt = 0; nt < 8; nt++)
                                yp[nt * 4] = make_float2(acc[mt][nt][half * 2],
                                                         acc[mt][nt][half * 2 + 1]);
                        }
                    }
                }
            }
        }

        tile = ntile;
    }
}

// ---------------------------------------------------------------------------
// Edge scatter-sum: g_h[dst[e],:] += g_v[src[e],:]. 8 edges per warp:
// uniform int4 index loads, 8 independent gathers (MLP=8), 8 RED.128/lane.
// ---------------------------------------------------------------------------
__global__ __launch_bounds__(256) void scatter_kernel(
    const int* __restrict__ src, const int* __restrict__ dst)
{
    const int w    = (int)((blockIdx.x * (unsigned)blockDim.x + threadIdx.x) >> 5);
    const int lane = threadIdx.x & 31;
    // 8 edges per warp; N_EDGES divisible by 8 -> no bounds check
    const int4 s0 = __ldg((const int4*)src + w * 2);
    const int4 s1 = __ldg((const int4*)src + w * 2 + 1);
    const int4 d0 = __ldg((const int4*)dst + w * 2);
    const int4 d1 = __ldg((const int4*)dst + w * 2 + 1);
    const int s[8] = {s0.x, s0.y, s0.z, s0.w, s1.x, s1.y, s1.z, s1.w};
    const int d[8] = {d0.x, d0.y, d0.z, d0.w, d1.x, d1.y, d1.z, d1.w};

    float4 x[8];
    #pragma unroll
    for (int i = 0; i < 8; i++)
        x[i] = ((const float4*)(g_v + (size_t)s[i] * DIM))[lane];

    #pragma unroll
    for (int i = 0; i < 8; i++) {
        float* hd = g_h + (size_t)d[i] * DIM + lane * 4;
        asm volatile("red.global.add.v4.f32 [%0], {%1, %2, %3, %4};"
                     :: "l"(hd), "f"(x[i].x), "f"(x[i].y), "f"(x[i].z), "f"(x[i].w)
                     : "memory");
    }
}

// ---------------------------------------------------------------------------
__global__ __launch_bounds__(256) void zero_h_kernel()
{
    const int i = blockIdx.x * blockDim.x + threadIdx.x;
    if (i < N_NODES * DIM / 4)
        ((float4*)g_h)[i] = make_float4(0.f, 0.f, 0.f, 0.f);
}

// ---------------------------------------------------------------------------
extern "C" void kernel_launch(void* const* d_in, const int* in_sizes, int n_in,
                              void* d_out, int out_size)
{
    const float* x     = (const float*)d_in[0];
    const int*   ntype = (const int*)  d_in[1];
    const int*   src   = (const int*)  d_in[2];
    const int*   dst   = (const int*)  d_in[3];
    const float* W_v   = (const float*)d_in[4];
    const float* W_a   = (const float*)d_in[5];
    float*       out   = (float*)d_out;

    float *v_ptr, *h_ptr;
    cudaGetSymbolAddress((void**)&v_ptr, g_v);
    cudaGetSymbolAddress((void**)&h_ptr, g_h);

    const int N = N_NODES;
    const int SMEM_DYN = 196608;   // Xhi+Xlo (64K) + W both types hi/lo (128K)
    cudaFuncSetAttribute(gemm_mma_kernel,
                         cudaFuncAttributeMaxDynamicSharedMemorySize, SMEM_DYN);

    // prepack W (bf16 hi/lo swizzled SMEM images)
    prepack_kernel<<<(4 * 2 * 128 * 128 + 255) / 256, 256>>>(W_v, W_a);
    // h = 0
    zero_h_kernel<<<(N_NODES * DIM / 4 + 255) / 256, 256>>>();
    // v = typed_linear(x, W_v, ntype)
    gemm_mma_kernel<<<148, 256, SMEM_DYN>>>(x, 0, ntype, v_ptr, N);
    // h[dst] += v[src]  (8 edges/warp: 800000/8 = 100000 warps = 12500 blocks)
    scatter_kernel<<<N_EDGES / 8 / 8, 256>>>(src, dst);
    // out = typed_linear(h, W_a, ntype)
    gemm_mma_kernel<<<148, 256, SMEM_DYN>>>(h_ptr, 1, ntype, out, N);
}